// round 9
// baseline (speedup 1.0000x reference)
#include <cuda_runtime.h>
#include <cuda_fp16.h>

#define N    512
#define NA   180
#define NCH  8
#define YPC  (N / NCH)   // 64 y-samples per chunk

// Scratch (no allocations allowed).
// pk[r*512+c]  = {h(img[r][c]), h(img[r][c+1]) | h(img[r+1][c]), h(img[r+1][c+1])}
// pkT = same built on the transposed image. Zero-padded at r+1==512 / c+1==512,
// which exactly matches the reference's zero-outside bilinear corners.
__device__ uint2 g_pk [N * N];
__device__ uint2 g_pkT[N * N];
__device__ float g_partial[NCH * N * NA];

__device__ __forceinline__ unsigned h2_bits(const __half2 h) {
    return *(const unsigned*)&h;
}

// ---------------------------------------------------------------------------
// Build packed 2x2 half table from img (row-major reads, coalesced).
// ---------------------------------------------------------------------------
__global__ void pack_k(const float* __restrict__ img) {
    const int c = blockIdx.x * blockDim.x + threadIdx.x;
    const int r = blockIdx.y;
    const bool c1ok = (c + 1) < N;
    const bool r1ok = (r + 1) < N;
    const float v00 = img[r * N + c];
    const float v01 = c1ok ? img[r * N + c + 1] : 0.0f;
    const float v10 = r1ok ? img[(r + 1) * N + c] : 0.0f;
    const float v11 = (r1ok && c1ok) ? img[(r + 1) * N + c + 1] : 0.0f;
    uint2 q;
    q.x = h2_bits(__floats2half2_rn(v00, v01));  // low=v00, high=v01
    q.y = h2_bits(__floats2half2_rn(v10, v11));  // low=v10, high=v11
    g_pk[r * N + c] = q;
}

// ---------------------------------------------------------------------------
// pkT[r][c] needs the 2x2 block of imgT at (r,c) = transpose of the 2x2 block
// of img at (c,r): (v00,v10 | v01,v11). So it's a tiled transpose of g_pk with
// a byte_perm component swizzle.
// ---------------------------------------------------------------------------
__global__ void packT_k() {
    __shared__ uint2 tile[32][33];
    int x  = blockIdx.x * 32 + threadIdx.x;
    int y0 = blockIdx.y * 32;
#pragma unroll
    for (int j = threadIdx.y; j < 32; j += 8)
        tile[j][threadIdx.x] = g_pk[(y0 + j) * N + x];
    __syncthreads();
    int xo  = blockIdx.y * 32 + threadIdx.x;
    int yo0 = blockIdx.x * 32;
#pragma unroll
    for (int j = threadIdx.y; j < 32; j += 8) {
        const uint2 q = tile[threadIdx.x][j];
        uint2 o;
        o.x = __byte_perm(q.x, q.y, 0x5410);  // (v00, v10)
        o.y = __byte_perm(q.x, q.y, 0x7632);  // (v01, v11)
        g_pkT[(yo0 + j) * N + xo] = o;
    }
}

// Checked float bilinear on the ORIGINAL image (boundary rim only).
__device__ __forceinline__ float sample_checked(const float* __restrict__ img,
                                                float row, float col) {
    const float rf = floorf(row), cf = floorf(col);
    const float wr = row - rf,    wc = col - cf;
    const int   ir = (int)rf,     ic = (int)cf;
    const bool r0 = (unsigned)ir       < (unsigned)N;
    const bool r1 = (unsigned)(ir + 1) < (unsigned)N;
    const bool c0 = (unsigned)ic       < (unsigned)N;
    const bool c1 = (unsigned)(ic + 1) < (unsigned)N;
    float v00 = (r0 && c0) ? img[(ir << 9) + ic]           : 0.0f;
    float v01 = (r0 && c1) ? img[(ir << 9) + ic + 1]       : 0.0f;
    float v10 = (r1 && c0) ? img[((ir + 1) << 9) + ic]     : 0.0f;
    float v11 = (r1 && c1) ? img[((ir + 1) << 9) + ic + 1] : 0.0f;
    const float top = fmaf(wc, v01 - v00, v00);
    const float bot = fmaf(wc, v11 - v10, v10);
    return fmaf(wr, bot - top, top);
}

// ---------------------------------------------------------------------------
// Radon: one thread = one (d, a), partial sum over a y-chunk.
// Interior sample = ONE LDG.64 from the packed table + 3 FMA.
// Per-angle fold (img vs imgT-packed, coords swapped) keeps the detector axis
// on the smaller row derivative. zbase lets us split chunks across launches.
// ---------------------------------------------------------------------------
__global__ void __launch_bounds__(128) radon_k(const float* __restrict__ img,
                                               const int*   __restrict__ angles,
                                               int zbase) {
    const int d  = blockIdx.x * blockDim.x + threadIdx.x;  // detector 0..511
    const int a  = blockIdx.y;                             // angle index
    const int ch = zbase + blockIdx.z;                     // y-chunk

    const float c = (N - 1) * 0.5f;
    const float t = (float)angles[a] * 0.017453292519943295f;
    float si, co;
    sincosf(t, &si, &co);

    const bool useT = fabsf(si) > fabsf(co);
    const uint2* __restrict__ pk = useT ? g_pkT : g_pk;

    const float xc = (float)d - c;
    // row = dr*yc + rbase ; col = dc*yc + cbase (in the chosen table's frame)
    float dr, rbase, dc, cbase;
    if (useT) { dr = si; rbase = fmaf( co, xc, c);
                dc = co; cbase = fmaf(-si, xc, c); }
    else      { dr = co; rbase = fmaf(-si, xc, c);
                dc = si; cbase = fmaf( co, xc, c); }

    float acc = 0.0f;
    const int ybeg = ch * YPC;
#pragma unroll 8
    for (int y = ybeg; y < ybeg + YPC; ++y) {
        const float yc  = (float)y - c;
        const float row = fmaf(dr, yc, rbase);
        const float col = fmaf(dc, yc, cbase);

        const float rf = floorf(row), cf = floorf(col);
        const float wr = row - rf,    wc = col - cf;
        const int   ir = (int)rf,     ic = (int)cf;

        if ((unsigned)ir < (unsigned)N && (unsigned)ic < (unsigned)N) {
            // fast path: one 8-byte load gives all 4 corners (edge-padded 0)
            const uint2 q = __ldg(pk + (ir << 9) + ic);
            const float2 tp = __half22float2(*(const __half2*)&q.x);
            const float2 bt = __half22float2(*(const __half2*)&q.y);
            const float top = fmaf(wc, tp.y - tp.x, tp.x);
            const float bot = fmaf(wc, bt.y - bt.x, bt.x);
            acc += fmaf(wr, bot - top, top);
        } else if (ir >= -1 && ic >= -1 && ir < N && ic < N) {
            // rim (ir==-1 or ic==-1): exact float path on the original image
            acc += useT ? sample_checked(img, col, row)
                        : sample_checked(img, row, col);
        }
        // else: sample fully outside -> contributes exactly 0
    }
    g_partial[(ch * N + d) * NA + a] = acc;
}

// ---------------------------------------------------------------------------
// Deterministic partial reduction: out[i] = sum over chunks (fixed order).
// ---------------------------------------------------------------------------
__global__ void reduce_k(float* __restrict__ out) {
    const int i = blockIdx.x * blockDim.x + threadIdx.x;
    if (i < N * NA) {
        const int d = i / NA;        // matches g_partial layout [(ch*N+d)*NA+a]
        const int a = i - d * NA;
        float s = 0.0f;
#pragma unroll
        for (int ch = 0; ch < NCH; ++ch)
            s += g_partial[(ch * N + d) * NA + a];
        out[i] = s;
    }
}

extern "C" void kernel_launch(void* const* d_in, const int* in_sizes, int n_in,
                              void* d_out, int out_size) {
    const float* img    = (const float*)d_in[0];
    const int*   angles = (const int*)d_in[1];
    float*       out    = (float*)d_out;

    pack_k <<<dim3(N / 128, N), 128>>>(img);
    packT_k<<<dim3(N / 32, N / 32), dim3(32, 8)>>>();
    // 3 radon launches (chunks 3+3+2): launch idx 3 overall = radon -> ncu
    // capture slot lands on the hot kernel.
    radon_k<<<dim3(N / 128, NA, 3), 128>>>(img, angles, 0);
    radon_k<<<dim3(N / 128, NA, 3), 128>>>(img, angles, 3);
    radon_k<<<dim3(N / 128, NA, 2), 128>>>(img, angles, 6);
    reduce_k<<<(N * NA + 255) / 256, 256>>>(out);
}

// round 12
// speedup vs baseline: 1.6144x; 1.6144x over previous
#include <cuda_runtime.h>
#include <cuda_fp16.h>

#define N    512
#define NA   180
#define NCH  8
#define YPC  (N / NCH)   // 64 y-samples per chunk
#define PAD  6
#define PKD  (N + 2 * PAD)   // 524: table coords -6..517, zero outside [-1,511]

// Scratch (no allocations allowed).
// Entry (r,c) (at [(r+PAD)*PKD + c+PAD]) packs the 2x2 bilinear corner block:
//   .x = half2( val(r,c),   val(r+1,c)   )   (v00, v10)
//   .y = half2( val(r,c+1), val(r+1,c+1) )   (v01, v11)
// val() is 0 outside [0,511]^2 -> zero rim exactly matches the reference's
// zero-outside bilinear corners, so NO boundary path is needed in radon.
__device__ uint2 g_pk [PKD * PKD];
__device__ uint2 g_pkT[PKD * PKD];
__device__ float g_partial[NCH * N * NA];

__device__ __forceinline__ unsigned h2_bits(const __half2 h) {
    return *(const unsigned*)&h;
}

// ---------------------------------------------------------------------------
// Build a padded packed table. T=0: img frame. T=1: transposed frame.
// ---------------------------------------------------------------------------
__global__ void pack_k(const float* __restrict__ img, int T) {
    const int ci = blockIdx.x * blockDim.x + threadIdx.x;
    const int ri = blockIdx.y;
    if (ci >= PKD) return;
    const int r = ri - PAD, c = ci - PAD;

    auto val = [&](int rr, int cc) -> float {
        if ((unsigned)rr >= (unsigned)N || (unsigned)cc >= (unsigned)N) return 0.0f;
        return T ? img[cc * N + rr] : img[rr * N + cc];
    };
    const float v00 = val(r, c),     v10 = val(r + 1, c);
    const float v01 = val(r, c + 1), v11 = val(r + 1, c + 1);
    uint2 q;
    q.x = h2_bits(__floats2half2_rn(v00, v10));
    q.y = h2_bits(__floats2half2_rn(v01, v11));
    (T ? g_pkT : g_pk)[ri * PKD + ci] = q;
}

// ---------------------------------------------------------------------------
// Radon: one thread = one (d, a), partial sum over a y-chunk.
// Branch-free body: one LDG.64, then FP32 lerp (half is storage-only).
// The y-window bounds ir,ic to [-2, 512]; the clamp below is never-binding
// safety over the FULL table extent [-PAD, N-1+PAD]. (R10/R11 bug: clamping
// to 511 aliased the legitimate all-zero ir=512 entry onto row 511 ->
// spurious edge contributions, rel_err 2.4e-3.)
// ---------------------------------------------------------------------------
__global__ void __launch_bounds__(128) radon_k(const int* __restrict__ angles,
                                               int zbase) {
    const int d  = blockIdx.x * blockDim.x + threadIdx.x;  // detector 0..511
    const int a  = blockIdx.y;                             // angle index
    const int ch = zbase + blockIdx.z;                     // y-chunk

    const float c = (N - 1) * 0.5f;
    const float t = (float)angles[a] * 0.017453292519943295f;
    float si, co;
    sincosf(t, &si, &co);

    const bool useT = fabsf(si) > fabsf(co);
    // offset to entry (0,0); indexing below uses ir*PKD + ic directly
    const uint2* __restrict__ pk =
        (useT ? g_pkT : g_pk) + (PAD * PKD + PAD);

    const float xc = (float)d - c;
    // row = dr*yc + rbase ; col = dc*yc + cbase (in the chosen table's frame)
    float dr, rbase, dc, cbase;
    if (useT) { dr = si; rbase = fmaf( co, xc, c);
                dc = co; cbase = fmaf(-si, xc, c); }
    else      { dr = co; rbase = fmaf(-si, xc, c);
                dc = si; cbase = fmaf( co, xc, c); }

    // ---- conservative contributing y-window (errors only add zero iters) ----
    const float inv_dr = 1.0f / dr;                 // |dr| >= 0.707 always
    const float e0 = fmaf(-1.5f - rbase, inv_dr, c);
    const float e1 = fmaf(512.5f - rbase, inv_dr, c);
    float ylo = fminf(e0, e1), yhi = fmaxf(e0, e1);
    if (fabsf(dc) > 1e-5f) {
        const float inv_dc = 1.0f / dc;
        const float f0 = fmaf(-1.5f - cbase, inv_dc, c);
        const float f1 = fmaf(512.5f - cbase, inv_dc, c);
        ylo = fmaxf(ylo, fminf(f0, f1));
        yhi = fminf(yhi, fmaxf(f0, f1));
    } else if (cbase <= -1.0f || cbase >= 512.0f) {
        yhi = ylo - 1.0f;                            // column misses image
    }
    const int ybeg = ch * YPC;
    const int y0 = max(ybeg,       (int)floorf(ylo));
    const int y1 = min(ybeg + YPC, (int)floorf(yhi) + 2);

    float acc = 0.0f;
#pragma unroll 8
    for (int y = y0; y < y1; ++y) {
        const float yc  = (float)y - c;
        const float row = fmaf(dr, yc, rbase);
        const float col = fmaf(dc, yc, cbase);

        int ir = __float2int_rd(row);
        int ic = __float2int_rd(col);
        const float wr = row - (float)ir;
        const float wc = col - (float)ic;
        ir = min(max(ir, -PAD), N - 1 + PAD);   // full table extent [-6, 517]
        ic = min(max(ic, -PAD), N - 1 + PAD);   // (entries >= 512 are all-zero)

        const uint2 q = __ldg(pk + ir * PKD + ic);
        const float2 pa = __half22float2(*(const __half2*)&q.x);  // (v00, v10)
        const float2 pb = __half22float2(*(const __half2*)&q.y);  // (v01, v11)
        const float top = fmaf(wc, pb.x - pa.x, pa.x);
        const float bot = fmaf(wc, pb.y - pa.y, pa.y);
        acc = fmaf(wr, bot - top, acc + top);
    }
    g_partial[(ch * N + d) * NA + a] = acc;
}

// ---------------------------------------------------------------------------
// Deterministic partial reduction: out[i] = sum over chunks (fixed order).
// ---------------------------------------------------------------------------
__global__ void reduce_k(float* __restrict__ out) {
    const int i = blockIdx.x * blockDim.x + threadIdx.x;
    if (i < N * NA) {
        const int d = i / NA;        // matches g_partial layout [(ch*N+d)*NA+a]
        const int a = i - d * NA;
        float s = 0.0f;
#pragma unroll
        for (int ch = 0; ch < NCH; ++ch)
            s += g_partial[(ch * N + d) * NA + a];
        out[i] = s;
    }
}

extern "C" void kernel_launch(void* const* d_in, const int* in_sizes, int n_in,
                              void* d_out, int out_size) {
    const float* img    = (const float*)d_in[0];
    const int*   angles = (const int*)d_in[1];
    float*       out    = (float*)d_out;

    const dim3 pg((PKD + 127) / 128, PKD);
    pack_k<<<pg, 128>>>(img, 0);
    pack_k<<<pg, 128>>>(img, 1);
    // launch idx 3 (= ncu capture slot) is the 6-chunk radon launch
    radon_k<<<dim3(N / 128, NA, 2), 128>>>(angles, 0);
    radon_k<<<dim3(N / 128, NA, 6), 128>>>(angles, 2);
    reduce_k<<<(N * NA + 255) / 256, 256>>>(out);
}

// round 13
// speedup vs baseline: 1.6376x; 1.0144x over previous
#include <cuda_runtime.h>
#include <cuda_fp16.h>

#define N    512
#define NA   180
#define NCH  8
#define YPC  (N / NCH)   // 64 y-samples per chunk
#define PAD  6
#define PKD  (N + 2 * PAD)   // 524: table coords -6..517, zero outside [-1,511]

// Scratch (no allocations allowed).
// Entry (r,c) (at [(r+PAD)*PKD + c+PAD]) packs the 2x2 bilinear corner block:
//   .x = half2( val(r,c),   val(r+1,c)   )   (v00, v10)
//   .y = half2( val(r,c+1), val(r+1,c+1) )   (v01, v11)
// val() is 0 outside [0,511]^2 -> zero rim exactly matches the reference's
// zero-outside bilinear corners, so NO boundary path is needed in radon.
__device__ uint2 g_pk [PKD * PKD];
__device__ uint2 g_pkT[PKD * PKD];
__device__ float g_partial[NCH * N * NA];

__device__ __forceinline__ unsigned h2_bits(const __half2 h) {
    return *(const unsigned*)&h;
}

// ---------------------------------------------------------------------------
// Build a padded packed table. T=0: img frame. T=1: transposed frame.
// ---------------------------------------------------------------------------
__global__ void pack_k(const float* __restrict__ img, int T) {
    const int ci = blockIdx.x * blockDim.x + threadIdx.x;
    const int ri = blockIdx.y;
    if (ci >= PKD) return;
    const int r = ri - PAD, c = ci - PAD;

    auto val = [&](int rr, int cc) -> float {
        if ((unsigned)rr >= (unsigned)N || (unsigned)cc >= (unsigned)N) return 0.0f;
        return T ? img[cc * N + rr] : img[rr * N + cc];
    };
    const float v00 = val(r, c),     v10 = val(r + 1, c);
    const float v01 = val(r, c + 1), v11 = val(r + 1, c + 1);
    uint2 q;
    q.x = h2_bits(__floats2half2_rn(v00, v10));
    q.y = h2_bits(__floats2half2_rn(v01, v11));
    (T ? g_pkT : g_pk)[ri * PKD + ci] = q;
}

// ---------------------------------------------------------------------------
// Radon: one thread = one (d, a), partial sum over a y-chunk.
// Branch-free body: one LDG.64 + FP32 lerp (half storage only). No index
// clamps: the y-window proves ir,ic in [-3,513], inside the padded table
// [-6,517]. Float y-stepping (yf += 1.0f, exact for ints <= 512) with the
// center fold absorbed into rbase2/cbase2. Two independent accumulator
// chains relax the per-iteration dependency.
// ---------------------------------------------------------------------------
__global__ void __launch_bounds__(128) radon_k(const int* __restrict__ angles,
                                               int zbase) {
    const int d  = blockIdx.x * blockDim.x + threadIdx.x;  // detector 0..511
    const int a  = blockIdx.y;                             // angle index
    const int ch = zbase + blockIdx.z;                     // y-chunk

    const float c = (N - 1) * 0.5f;
    const float t = (float)angles[a] * 0.017453292519943295f;
    float si, co;
    sincosf(t, &si, &co);

    const bool useT = fabsf(si) > fabsf(co);
    // offset to entry (0,0); indexing below uses ir*PKD + ic directly
    const uint2* __restrict__ pk =
        (useT ? g_pkT : g_pk) + (PAD * PKD + PAD);

    const float xc = (float)d - c;
    // row = dr*yc + rbase ; col = dc*yc + cbase (in the chosen table's frame)
    float dr, rbase, dc, cbase;
    if (useT) { dr = si; rbase = fmaf( co, xc, c);
                dc = co; cbase = fmaf(-si, xc, c); }
    else      { dr = co; rbase = fmaf(-si, xc, c);
                dc = si; cbase = fmaf( co, xc, c); }

    // ---- conservative contributing y-window (errors only add zero iters) ----
    const float inv_dr = 1.0f / dr;                 // |dr| >= 0.707 always
    const float e0 = fmaf(-1.5f - rbase, inv_dr, c);
    const float e1 = fmaf(512.5f - rbase, inv_dr, c);
    float ylo = fminf(e0, e1), yhi = fmaxf(e0, e1);
    if (fabsf(dc) > 1e-5f) {
        const float inv_dc = 1.0f / dc;
        const float f0 = fmaf(-1.5f - cbase, inv_dc, c);
        const float f1 = fmaf(512.5f - cbase, inv_dc, c);
        ylo = fmaxf(ylo, fminf(f0, f1));
        yhi = fminf(yhi, fmaxf(f0, f1));
    } else if (cbase <= -1.0f || cbase >= 512.0f) {
        yhi = ylo - 1.0f;                            // column misses image
    }
    const int ybeg = ch * YPC;
    const int y0 = max(ybeg,       (int)floorf(ylo));
    const int y1 = min(ybeg + YPC, (int)floorf(yhi) + 2);

    // fold the center: row = dr*yf + rbase2 with yf = y (exact float ints)
    const float rbase2 = fmaf(-dr, c, rbase);
    const float cbase2 = fmaf(-dc, c, cbase);

    float accT = 0.0f;   // sum of top terms        (FADD chain)
    float accF = 0.0f;   // sum of wr*(bot-top)     (FFMA chain)
    float yf = (float)y0;
#pragma unroll 8
    for (int y = y0; y < y1; ++y) {
        const float row = fmaf(dr, yf, rbase2);
        const float col = fmaf(dc, yf, cbase2);
        yf += 1.0f;

        const int ir = __float2int_rd(row);
        const int ic = __float2int_rd(col);
        const float wr = row - (float)ir;
        const float wc = col - (float)ic;

        const uint2 q = __ldg(pk + ir * PKD + ic);
        const float2 pa = __half22float2(*(const __half2*)&q.x);  // (v00, v10)
        const float2 pb = __half22float2(*(const __half2*)&q.y);  // (v01, v11)
        const float top = fmaf(wc, pb.x - pa.x, pa.x);
        const float bot = fmaf(wc, pb.y - pa.y, pa.y);
        accT += top;
        accF = fmaf(wr, bot - top, accF);
    }
    g_partial[(ch * N + d) * NA + a] = accT + accF;
}

// ---------------------------------------------------------------------------
// Deterministic partial reduction: out[i] = sum over chunks (fixed order).
// ---------------------------------------------------------------------------
__global__ void reduce_k(float* __restrict__ out) {
    const int i = blockIdx.x * blockDim.x + threadIdx.x;
    if (i < N * NA) {
        const int d = i / NA;        // matches g_partial layout [(ch*N+d)*NA+a]
        const int a = i - d * NA;
        float s = 0.0f;
#pragma unroll
        for (int ch = 0; ch < NCH; ++ch)
            s += g_partial[(ch * N + d) * NA + a];
        out[i] = s;
    }
}

extern "C" void kernel_launch(void* const* d_in, const int* in_sizes, int n_in,
                              void* d_out, int out_size) {
    const float* img    = (const float*)d_in[0];
    const int*   angles = (const int*)d_in[1];
    float*       out    = (float*)d_out;

    const dim3 pg((PKD + 127) / 128, PKD);
    pack_k<<<pg, 128>>>(img, 0);
    pack_k<<<pg, 128>>>(img, 1);
    // launch idx 3 (= ncu capture slot) is the 6-chunk radon launch
    radon_k<<<dim3(N / 128, NA, 2), 128>>>(angles, 0);
    radon_k<<<dim3(N / 128, NA, 6), 128>>>(angles, 2);
    reduce_k<<<(N * NA + 255) / 256, 256>>>(out);
}